// round 14
// baseline (speedup 1.0000x reference)
#include <cuda_runtime.h>
#include <cuda_fp16.h>
#include <cstdint>
#include <cstddef>

// ============================================================================
// SpanMarkerV1 on sm_100: fp16 mma.sync m16n8k16, fp32 accum.
//   B=8, L=512, D=768, S=6144, H=3072
// Pipeline: L1 fused pair GEMM -> L2 z-batched GEMM -> U/V projections (fp16,
//   ob1 folded into U) -> final GEMM with gather+add+relu fused into A staging.
// GEMM core: 128x128x64 tiles, 32x64 warp tiles, 3-stage cp.async ring
// (round-11 end-of-loop staging order -- round-12 early order regressed),
// ldmatrix.x4, stride-72-half smem, 2 CTAs/SM.
// ============================================================================

#define BM 128
#define BN 128
#define BK 64
#define LSTR 72                         // halves; 144B row stride, conflict-free
#define STAGE_H (BM * LSTR)             // 9216 halves per operand tile
#define STAGE_ALL (2 * STAGE_H)         // A + B per stage (halves)
#define NSTAGE 3
#define GSMEM_BYTES (NSTAGE * STAGE_ALL * 2)  // 110592 bytes

// -------- scratch (device globals; allocations are forbidden) ---------------
__device__ __half g_hidden[25165824ULL];  // [4096,6144] L1 output
__device__ __half g_serelu[6291456ULL];   // [2][4096,768] relu'd reps
__device__ __half g_hh[3145728ULL];       // h in fp16
__device__ __half g_w1cat[4718592ULL];    // [6144,768]  = [sw1t; ew1t]
__device__ __half g_w2cat[4718592ULL];    // [1536,3072] = [sw2t; ew2t]
__device__ __half g_ow1t[4718592ULL];     // [3072,1536]
__device__ __half g_ow2t[2359296ULL];     // [768,3072]
__device__ __half g_uv[25165824ULL];      // [2][4096,3072] fp16 U(+ob1), V
__device__ float  g_b1cat[6144];
__device__ float  g_b2cat[1536];
__device__ float  g_zbias[3072];          // zero-initialized

__device__ __forceinline__ void cp16(uint32_t smem_addr, const void* gmem_ptr) {
    asm volatile("cp.async.cg.shared.global [%0], [%1], 16;\n" :: "r"(smem_addr), "l"(gmem_ptr));
}

__device__ __forceinline__ void ldsm4(uint32_t* r, uint32_t addr) {
    asm volatile("ldmatrix.sync.aligned.m8n8.x4.shared.b16 {%0,%1,%2,%3}, [%4];"
                 : "=r"(r[0]), "=r"(r[1]), "=r"(r[2]), "=r"(r[3]) : "r"(addr));
}

__device__ __forceinline__ void mma_f16(float c[4], const uint32_t a[4], const uint32_t b[2]) {
    asm volatile(
        "mma.sync.aligned.m16n8k16.row.col.f32.f16.f16.f32 "
        "{%0,%1,%2,%3}, {%4,%5,%6,%7}, {%8,%9}, {%0,%1,%2,%3};\n"
        : "+f"(c[0]), "+f"(c[1]), "+f"(c[2]), "+f"(c[3])
        : "r"(a[0]), "r"(a[1]), "r"(a[2]), "r"(a[3]),
          "r"(b[0]), "r"(b[1]));
}

// ============================================================================
// Shared GEMM mainloop+epilogue (round-11 staging order).
// ============================================================================
__device__ __forceinline__ void gemm_core(
    const __half* __restrict__ A, int lda, const __half* __restrict__ Bt, int ldb,
    const float* __restrict__ bias, void* __restrict__ Cv, int ldc,
    int K, int relu, int c_half, int tileM, int tileN, uint32_t sbase)
{
    const int tid  = threadIdx.x;
    const int warp = tid >> 5;
    const int lane = tid & 31;
    const int wm = warp & 3;
    const int wn = warp >> 2;

    float acc[2][8][4];
#pragma unroll
    for (int mi = 0; mi < 2; mi++)
#pragma unroll
        for (int ni = 0; ni < 8; ni++)
#pragma unroll
            for (int j = 0; j < 4; j++) acc[mi][ni][j] = 0.0f;

    auto stage = [&](int s, int k0) {
        const uint32_t abase = sbase + s * (STAGE_ALL * 2);
        const uint32_t bbase = abase + STAGE_H * 2;
#pragma unroll
        for (int i = 0; i < 4; i++) {
            int ch  = tid + i * 256;
            int row = ch >> 3;
            int co  = (ch & 7) << 3;
            cp16(abase + (row * LSTR + co) * 2, A  + (size_t)(tileM + row) * lda + k0 + co);
            cp16(bbase + (row * LSTR + co) * 2, Bt + (size_t)(tileN + row) * ldb + k0 + co);
        }
        asm volatile("cp.async.commit_group;\n" ::);
    };

    const int arow = lane & 15;
    const int acol = (lane >> 4) << 3;
    const int bg   = lane >> 3;
    const int brow = ((bg >> 1) << 3) + (lane & 7);
    const int bcol = (bg & 1) << 3;

    const int KT = K / BK;
    stage(0, 0);
    stage(1, BK);

    int cons = 0, ss = 2;
    for (int kt = 0; kt < KT; kt++) {
        if (kt + 1 < KT) asm volatile("cp.async.wait_group 1;\n" ::);
        else             asm volatile("cp.async.wait_group 0;\n" ::);
        __syncthreads();

        const uint32_t abase = sbase + cons * (STAGE_ALL * 2);
        const uint32_t bbase = abase + STAGE_H * 2;

#pragma unroll
        for (int kk = 0; kk < 4; kk++) {
            const int kb = kk << 4;
            uint32_t af[2][4], bf[8][2];
#pragma unroll
            for (int mi = 0; mi < 2; mi++) {
                int m0 = wm * 32 + mi * 16;
                ldsm4(af[mi], abase + ((m0 + arow) * LSTR + kb + acol) * 2);
            }
#pragma unroll
            for (int p = 0; p < 4; p++) {
                int n0 = wn * 64 + p * 16;
                uint32_t r[4];
                ldsm4(r, bbase + ((n0 + brow) * LSTR + kb + bcol) * 2);
                bf[2 * p][0] = r[0]; bf[2 * p][1] = r[1];
                bf[2 * p + 1][0] = r[2]; bf[2 * p + 1][1] = r[3];
            }
#pragma unroll
            for (int mi = 0; mi < 2; mi++)
#pragma unroll
                for (int ni = 0; ni < 8; ni++)
                    mma_f16(acc[mi][ni], af[mi], bf[ni]);
        }

        if (kt + 2 < KT) stage(ss, (kt + 2) * BK);
        if (++cons == NSTAGE) cons = 0;
        if (++ss == NSTAGE) ss = 0;
    }

#pragma unroll
    for (int mi = 0; mi < 2; mi++) {
#pragma unroll
        for (int ni = 0; ni < 8; ni++) {
            int m = tileM + wm * 32 + mi * 16 + (lane >> 2);
            int n = tileN + wn * 64 + ni * 8 + ((lane & 3) << 1);
            float b0 = bias[n], b1 = bias[n + 1];
            float v0 = acc[mi][ni][0] + b0;
            float v1 = acc[mi][ni][1] + b1;
            float v2 = acc[mi][ni][2] + b0;
            float v3 = acc[mi][ni][3] + b1;
            if (relu) {
                v0 = fmaxf(v0, 0.0f); v1 = fmaxf(v1, 0.0f);
                v2 = fmaxf(v2, 0.0f); v3 = fmaxf(v3, 0.0f);
            }
            if (c_half) {
                __half* C = (__half*)Cv;
                *(__half2*)&C[(size_t)m * ldc + n]       = __floats2half2_rn(v0, v1);
                *(__half2*)&C[(size_t)(m + 8) * ldc + n] = __floats2half2_rn(v2, v3);
            } else {
                float* C = (float*)Cv;
                *(float2*)&C[(size_t)m * ldc + n]       = make_float2(v0, v1);
                *(float2*)&C[(size_t)(m + 8) * ldc + n] = make_float2(v2, v3);
            }
        }
    }
}

// ---- general GEMM wrapper ---------------------------------------------------
__global__ __launch_bounds__(256, 2)
void gemm_k(const __half* __restrict__ A, int lda, const __half* __restrict__ Bt,
            const float* __restrict__ bias, void* __restrict__ Cv, int ldc,
            int K, int relu, int c_half)
{
    extern __shared__ __half sm[];
    gemm_core(A, lda, Bt, K, bias, Cv, ldc, K, relu, c_half,
              blockIdx.y * BM, blockIdx.x * BN,
              (uint32_t)__cvta_generic_to_shared(sm));
}

// ---- layer-2 pair, z-batched ------------------------------------------------
__global__ __launch_bounds__(256, 2)
void gemm_l2(const __half* __restrict__ hidden, const __half* __restrict__ w2cat,
             const float* __restrict__ b2cat, __half* __restrict__ serelu)
{
    extern __shared__ __half sm[];
    const int z = blockIdx.z;
    gemm_core(hidden + z * 3072, 6144,
              w2cat + (size_t)z * 768 * 3072, 3072,
              b2cat + z * 768,
              serelu + (size_t)z * 4096 * 768, 768,
              3072, 1, 1,
              blockIdx.y * BM, blockIdx.x * BN,
              (uint32_t)__cvta_generic_to_shared(sm));
}

// ---- U/V pair, z-batched (fp16 out); U (z=0) gets ob1 folded in -------------
__global__ __launch_bounds__(256, 2)
void gemm_uv(const __half* __restrict__ serelu, const __half* __restrict__ ow1t,
             const float* __restrict__ ob1, const float* __restrict__ zbias,
             __half* __restrict__ uv)
{
    extern __shared__ __half sm[];
    const int z = blockIdx.z;
    gemm_core(serelu + (size_t)z * 4096 * 768, 768,
              ow1t + z * 768, 1536,           // K-offset into [3072,1536] K-major
              z == 0 ? ob1 : zbias,
              uv + (size_t)z * 4096 * 3072, 3072,
              768, 0, 1,
              blockIdx.y * BM, blockIdx.x * BN,
              (uint32_t)__cvta_generic_to_shared(sm));
}

// ============================================================================
// Final GEMM with fused gather+add+relu A staging:
//   A row r = relu(U[b,i0(r),:] + V[b,i1(r),:])   (U already includes ob1)
//   out[49152,768] = A @ ow2t + ob2   (fp32 out)
// ============================================================================
__global__ __launch_bounds__(256, 2)
void gemm_final(const __half* __restrict__ uv, const int* __restrict__ span,
                const __half* __restrict__ Bt, const float* __restrict__ bias,
                float* __restrict__ out)
{
    extern __shared__ __half sm[];
    const uint32_t sbase = (uint32_t)__cvta_generic_to_shared(sm);
    __shared__ int sidx[2 * BM];

    const int tid  = threadIdx.x;
    const int warp = tid >> 5;
    const int lane = tid & 31;
    const int wm = warp & 3;
    const int wn = warp >> 2;
    const int tileM = blockIdx.y * BM;
    const int tileN = blockIdx.x * BN;
    const int b512 = (tileM / 6144) * 512;

    const __half* __restrict__ U = uv;
    const __half* __restrict__ V = uv + (size_t)4096 * 3072;

    if (tid < BM) {
        sidx[2 * tid]     = span[2 * (size_t)(tileM + tid)];
        sidx[2 * tid + 1] = span[2 * (size_t)(tileM + tid) + 1];
    }
    __syncthreads();

    float acc[2][8][4];
#pragma unroll
    for (int mi = 0; mi < 2; mi++)
#pragma unroll
        for (int ni = 0; ni < 8; ni++)
#pragma unroll
            for (int j = 0; j < 4; j++) acc[mi][ni][j] = 0.0f;

    const int K = 3072;
    const __half2 hz = __floats2half2_rn(0.0f, 0.0f);

    // A: gather two rows, fp16 add + relu, STS.  B: cp.async as usual.
    auto stage = [&](int s, int k0) {
        const uint32_t bbase = sbase + s * (STAGE_ALL * 2) + STAGE_H * 2;
#pragma unroll 2
        for (int i = 0; i < 4; i++) {
            int ch  = tid + i * 256;
            int row = ch >> 3;
            int co  = (ch & 7) << 3;
            uint4 u = *(const uint4*)(U + (size_t)(b512 + sidx[2 * row])     * 3072 + k0 + co);
            uint4 v = *(const uint4*)(V + (size_t)(b512 + sidx[2 * row + 1]) * 3072 + k0 + co);
            const __half2* up = (const __half2*)&u;
            const __half2* vp = (const __half2*)&v;
            uint4 w;
            __half2* wp = (__half2*)&w;
#pragma unroll
            for (int j = 0; j < 4; j++)
                wp[j] = __hmax2(__hadd2(up[j], vp[j]), hz);
            *(uint4*)&sm[s * STAGE_ALL + row * LSTR + co] = w;
        }
#pragma unroll
        for (int i = 0; i < 4; i++) {
            int ch  = tid + i * 256;
            int row = ch >> 3;
            int co  = (ch & 7) << 3;
            cp16(bbase + (row * LSTR + co) * 2, Bt + (size_t)(tileN + row) * K + k0 + co);
        }
        asm volatile("cp.async.commit_group;\n" ::);
    };

    const int arow = lane & 15;
    const int acol = (lane >> 4) << 3;
    const int bg   = lane >> 3;
    const int brow = ((bg >> 1) << 3) + (lane & 7);
    const int bcol = (bg & 1) << 3;

    const int KT = K / BK;   // 48
    stage(0, 0);
    stage(1, BK);

    int cons = 0, ss = 2;
    for (int kt = 0; kt < KT; kt++) {
        if (kt + 1 < KT) asm volatile("cp.async.wait_group 1;\n" ::);
        else             asm volatile("cp.async.wait_group 0;\n" ::);
        __syncthreads();

        const uint32_t abase = sbase + cons * (STAGE_ALL * 2);
        const uint32_t bbase = abase + STAGE_H * 2;

#pragma unroll
        for (int kk = 0; kk < 4; kk++) {
            const int kb = kk << 4;
            uint32_t af[2][4], bf[8][2];
#pragma unroll
            for (int mi = 0; mi < 2; mi++) {
                int m0 = wm * 32 + mi * 16;
                ldsm4(af[mi], abase + ((m0 + arow) * LSTR + kb + acol) * 2);
            }
#pragma unroll
            for (int p = 0; p < 4; p++) {
                int n0 = wn * 64 + p * 16;
                uint32_t r[4];
                ldsm4(r, bbase + ((n0 + brow) * LSTR + kb + bcol) * 2);
                bf[2 * p][0] = r[0]; bf[2 * p][1] = r[1];
                bf[2 * p + 1][0] = r[2]; bf[2 * p + 1][1] = r[3];
            }
#pragma unroll
            for (int mi = 0; mi < 2; mi++)
#pragma unroll
                for (int ni = 0; ni < 8; ni++)
                    mma_f16(acc[mi][ni], af[mi], bf[ni]);
        }

        if (kt + 2 < KT) stage(ss, (kt + 2) * BK);
        if (++cons == NSTAGE) cons = 0;
        if (++ss == NSTAGE) ss = 0;
    }

#pragma unroll
    for (int mi = 0; mi < 2; mi++) {
#pragma unroll
        for (int ni = 0; ni < 8; ni++) {
            int m = tileM + wm * 32 + mi * 16 + (lane >> 2);
            int n = tileN + wn * 64 + ni * 8 + ((lane & 3) << 1);
            float v0 = acc[mi][ni][0] + bias[n];
            float v1 = acc[mi][ni][1] + bias[n + 1];
            float v2 = acc[mi][ni][2] + bias[n];
            float v3 = acc[mi][ni][3] + bias[n + 1];
            *(float2*)&out[(size_t)m * 768 + n]       = make_float2(v0, v1);
            *(float2*)&out[(size_t)(m + 8) * 768 + n] = make_float2(v2, v3);
        }
    }
}

// ---- fused weight prep: all 6 transposes (+fp16) in ONE launch --------------
__global__ void transpose_all(const float* sw1, const float* ew1, const float* ow1,
                              const float* sw2, const float* ew2, const float* ow2,
                              __half* w1cat, __half* w2cat, __half* ow1t, __half* ow2t)
{
    const float* in; __half* out; int R, C;
    switch (blockIdx.z) {
        case 0: in = sw1; out = w1cat;                          R =  768; C = 3072; break;
        case 1: in = ew1; out = w1cat + (size_t)3072 * 768;     R =  768; C = 3072; break;
        case 2: in = ow1; out = ow1t;                           R = 1536; C = 3072; break;
        case 3: in = sw2; out = w2cat;                          R = 3072; C =  768; break;
        case 4: in = ew2; out = w2cat + (size_t)768 * 3072;     R = 3072; C =  768; break;
        default:in = ow2; out = ow2t;                           R = 3072; C =  768; break;
    }
    const int x0 = blockIdx.x * 32, y0 = blockIdx.y * 32;
    if (x0 >= C || y0 >= R) return;

    __shared__ float t[32][33];
    const int tx = threadIdx.x, ty = threadIdx.y;   // 32 x 8
#pragma unroll
    for (int i = 0; i < 32; i += 8)
        t[ty + i][tx] = in[(size_t)(y0 + ty + i) * C + x0 + tx];
    __syncthreads();
#pragma unroll
    for (int i = 0; i < 32; i += 8)
        out[(size_t)(x0 + ty + i) * R + y0 + tx] = __float2half_rn(t[tx][ty + i]);
}

// ---- bias concats + h convert ----------------------------------------------
__global__ void bias_cat(const float* sb1, const float* eb1, const float* sb2, const float* eb2,
                         float* b1cat, float* b2cat)
{
    int i = blockIdx.x * 256 + threadIdx.x;
    if (i < 3072) { b1cat[i] = sb1[i]; b1cat[3072 + i] = eb1[i]; }
    if (i < 768)  { b2cat[i] = sb2[i]; b2cat[768 + i]  = eb2[i]; }
}

__global__ void f2h_kernel(const float* __restrict__ in, __half* __restrict__ out, int n)
{
    int i = blockIdx.x * 256 + threadIdx.x;
    if (i < n) out[i] = __float2half_rn(in[i]);
}

extern "C" void kernel_launch(void* const* d_in, const int* in_sizes, int n_in,
                              void* d_out, int out_size)
{
    const float* h    = (const float*)d_in[0];
    const int*   span = (const int*)  d_in[1];
    const float* sw1  = (const float*)d_in[2];
    const float* sb1  = (const float*)d_in[3];
    const float* sw2  = (const float*)d_in[4];
    const float* sb2  = (const float*)d_in[5];
    const float* ew1  = (const float*)d_in[6];
    const float* eb1  = (const float*)d_in[7];
    const float* ew2  = (const float*)d_in[8];
    const float* eb2  = (const float*)d_in[9];
    const float* ow1  = (const float*)d_in[10];
    const float* ob1  = (const float*)d_in[11];
    const float* ow2  = (const float*)d_in[12];
    const float* ob2  = (const float*)d_in[13];
    float* out = (float*)d_out;

    __half *hidden, *serelu, *hh, *w1cat, *w2cat, *ow1t, *ow2t, *uv;
    float *b1cat, *b2cat, *zbias;
    cudaGetSymbolAddress((void**)&hidden, g_hidden);
    cudaGetSymbolAddress((void**)&serelu, g_serelu);
    cudaGetSymbolAddress((void**)&hh,     g_hh);
    cudaGetSymbolAddress((void**)&w1cat,  g_w1cat);
    cudaGetSymbolAddress((void**)&w2cat,  g_w2cat);
    cudaGetSymbolAddress((void**)&ow1t,   g_ow1t);
    cudaGetSymbolAddress((void**)&ow2t,   g_ow2t);
    cudaGetSymbolAddress((void**)&uv,     g_uv);
    cudaGetSymbolAddress((void**)&b1cat,  g_b1cat);
    cudaGetSymbolAddress((void**)&b2cat,  g_b2cat);
    cudaGetSymbolAddress((void**)&zbias,  g_zbias);

    cudaFuncSetAttribute(gemm_k,     cudaFuncAttributeMaxDynamicSharedMemorySize, GSMEM_BYTES);
    cudaFuncSetAttribute(gemm_l2,    cudaFuncAttributeMaxDynamicSharedMemorySize, GSMEM_BYTES);
    cudaFuncSetAttribute(gemm_uv,    cudaFuncAttributeMaxDynamicSharedMemorySize, GSMEM_BYTES);
    cudaFuncSetAttribute(gemm_final, cudaFuncAttributeMaxDynamicSharedMemorySize, GSMEM_BYTES);

    // 1: weight transposes   2: bias concats   3: h -> fp16
    transpose_all<<<dim3(96, 96, 6), dim3(32, 8)>>>(sw1, ew1, ow1, sw2, ew2, ow2,
                                                    w1cat, w2cat, ow1t, ow2t);
    bias_cat<<<12, 256>>>(sb1, eb1, sb2, eb2, b1cat, b2cat);
    f2h_kernel<<<(3145728 + 255) / 256, 256>>>(h, hh, 3145728);

    const dim3 blk(256);
    // 4: fused layer-1  hidden_se[4096,6144] = relu(hh @ w1cat + b1cat)
    gemm_k<<<dim3(48, 32), blk, GSMEM_BYTES>>>(hh, 768, w1cat, b1cat, hidden, 6144,
                                               768, 1, 1);
    // 5: batched layer-2  serelu[z] = relu(hidden_se[:, z] @ w2cat[z] + b2cat[z])
    gemm_l2<<<dim3(6, 32, 2), blk, GSMEM_BYTES>>>(hidden, w2cat, b2cat, serelu);
    // 6: U/V projections (fp16); U gets ob1 in epilogue
    gemm_uv<<<dim3(24, 32, 2), blk, GSMEM_BYTES>>>(serelu, ow1t, ob1, zbias, uv);
    // 7: final GEMM with fused gather  out = relu(U[i0]+V[i1]) @ ow2t + ob2
    gemm_final<<<dim3(6, 384), blk, GSMEM_BYTES>>>(uv, span, ow2t, ob2, out);
}

// round 15
// speedup vs baseline: 1.1826x; 1.1826x over previous
#include <cuda_runtime.h>
#include <cuda_fp16.h>
#include <cstdint>
#include <cstddef>

// ============================================================================
// SpanMarkerV1 on sm_100: fp16 mma.sync m16n8k16, fp32 accum.
//   B=8, L=512, D=768, S=6144, H=3072
// Pipeline: L1 fused pair GEMM -> L2 z-batched GEMM -> U/V projections (fp16,
//   ob1 folded into U) -> gather+add+relu bandwidth pass -> final GEMM.
// (Round-14 lesson: gather fused into GEMM A-staging regresses -- synchronous
// LDG/STS on the critical path loses to cp.async; keep the separate pass.)
// GEMM core: 128x128x64 tiles, 32x64 warp tiles, 3-stage cp.async ring with
// end-of-loop staging (round-12 early staging regressed), ldmatrix.x4,
// stride-72-half smem, 2 CTAs/SM.
// ============================================================================

#define BM 128
#define BN 128
#define BK 64
#define LSTR 72                         // halves; 144B row stride, conflict-free
#define STAGE_H (BM * LSTR)             // 9216 halves per operand tile
#define STAGE_ALL (2 * STAGE_H)         // A + B per stage (halves)
#define NSTAGE 3
#define GSMEM_BYTES (NSTAGE * STAGE_ALL * 2)  // 110592 bytes

// -------- scratch (device globals; allocations are forbidden) ---------------
__device__ __half g_hidden[150994944ULL]; // [4096,6144] L1 out, then [49152,3072]
__device__ __half g_serelu[6291456ULL];   // [2][4096,768] relu'd reps
__device__ __half g_hh[3145728ULL];       // h in fp16
__device__ __half g_w1cat[4718592ULL];    // [6144,768]  = [sw1t; ew1t]
__device__ __half g_w2cat[4718592ULL];    // [1536,3072] = [sw2t; ew2t]
__device__ __half g_ow1t[4718592ULL];     // [3072,1536]
__device__ __half g_ow2t[2359296ULL];     // [768,3072]
__device__ __half g_uv[25165824ULL];      // [2][4096,3072] fp16 U(+ob1), V
__device__ float  g_b1cat[6144];
__device__ float  g_b2cat[1536];
__device__ float  g_zbias[3072];          // zero-initialized

__device__ __forceinline__ void cp16(uint32_t smem_addr, const void* gmem_ptr) {
    asm volatile("cp.async.cg.shared.global [%0], [%1], 16;\n" :: "r"(smem_addr), "l"(gmem_ptr));
}

__device__ __forceinline__ void ldsm4(uint32_t* r, uint32_t addr) {
    asm volatile("ldmatrix.sync.aligned.m8n8.x4.shared.b16 {%0,%1,%2,%3}, [%4];"
                 : "=r"(r[0]), "=r"(r[1]), "=r"(r[2]), "=r"(r[3]) : "r"(addr));
}

__device__ __forceinline__ void mma_f16(float c[4], const uint32_t a[4], const uint32_t b[2]) {
    asm volatile(
        "mma.sync.aligned.m16n8k16.row.col.f32.f16.f16.f32 "
        "{%0,%1,%2,%3}, {%4,%5,%6,%7}, {%8,%9}, {%0,%1,%2,%3};\n"
        : "+f"(c[0]), "+f"(c[1]), "+f"(c[2]), "+f"(c[3])
        : "r"(a[0]), "r"(a[1]), "r"(a[2]), "r"(a[3]),
          "r"(b[0]), "r"(b[1]));
}

// ============================================================================
// Shared GEMM mainloop+epilogue (round-11 staging order).
// ============================================================================
__device__ __forceinline__ void gemm_core(
    const __half* __restrict__ A, int lda, const __half* __restrict__ Bt, int ldb,
    const float* __restrict__ bias, void* __restrict__ Cv, int ldc,
    int K, int relu, int c_half, int tileM, int tileN, uint32_t sbase)
{
    const int tid  = threadIdx.x;
    const int warp = tid >> 5;
    const int lane = tid & 31;
    const int wm = warp & 3;
    const int wn = warp >> 2;

    float acc[2][8][4];
#pragma unroll
    for (int mi = 0; mi < 2; mi++)
#pragma unroll
        for (int ni = 0; ni < 8; ni++)
#pragma unroll
            for (int j = 0; j < 4; j++) acc[mi][ni][j] = 0.0f;

    auto stage = [&](int s, int k0) {
        const uint32_t abase = sbase + s * (STAGE_ALL * 2);
        const uint32_t bbase = abase + STAGE_H * 2;
#pragma unroll
        for (int i = 0; i < 4; i++) {
            int ch  = tid + i * 256;
            int row = ch >> 3;
            int co  = (ch & 7) << 3;
            cp16(abase + (row * LSTR + co) * 2, A  + (size_t)(tileM + row) * lda + k0 + co);
            cp16(bbase + (row * LSTR + co) * 2, Bt + (size_t)(tileN + row) * ldb + k0 + co);
        }
        asm volatile("cp.async.commit_group;\n" ::);
    };

    const int arow = lane & 15;
    const int acol = (lane >> 4) << 3;
    const int bg   = lane >> 3;
    const int brow = ((bg >> 1) << 3) + (lane & 7);
    const int bcol = (bg & 1) << 3;

    const int KT = K / BK;
    stage(0, 0);
    stage(1, BK);

    int cons = 0, ss = 2;
    for (int kt = 0; kt < KT; kt++) {
        if (kt + 1 < KT) asm volatile("cp.async.wait_group 1;\n" ::);
        else             asm volatile("cp.async.wait_group 0;\n" ::);
        __syncthreads();

        const uint32_t abase = sbase + cons * (STAGE_ALL * 2);
        const uint32_t bbase = abase + STAGE_H * 2;

#pragma unroll
        for (int kk = 0; kk < 4; kk++) {
            const int kb = kk << 4;
            uint32_t af[2][4], bf[8][2];
#pragma unroll
            for (int mi = 0; mi < 2; mi++) {
                int m0 = wm * 32 + mi * 16;
                ldsm4(af[mi], abase + ((m0 + arow) * LSTR + kb + acol) * 2);
            }
#pragma unroll
            for (int p = 0; p < 4; p++) {
                int n0 = wn * 64 + p * 16;
                uint32_t r[4];
                ldsm4(r, bbase + ((n0 + brow) * LSTR + kb + bcol) * 2);
                bf[2 * p][0] = r[0]; bf[2 * p][1] = r[1];
                bf[2 * p + 1][0] = r[2]; bf[2 * p + 1][1] = r[3];
            }
#pragma unroll
            for (int mi = 0; mi < 2; mi++)
#pragma unroll
                for (int ni = 0; ni < 8; ni++)
                    mma_f16(acc[mi][ni], af[mi], bf[ni]);
        }

        if (kt + 2 < KT) stage(ss, (kt + 2) * BK);
        if (++cons == NSTAGE) cons = 0;
        if (++ss == NSTAGE) ss = 0;
    }

#pragma unroll
    for (int mi = 0; mi < 2; mi++) {
#pragma unroll
        for (int ni = 0; ni < 8; ni++) {
            int m = tileM + wm * 32 + mi * 16 + (lane >> 2);
            int n = tileN + wn * 64 + ni * 8 + ((lane & 3) << 1);
            float b0 = bias[n], b1 = bias[n + 1];
            float v0 = acc[mi][ni][0] + b0;
            float v1 = acc[mi][ni][1] + b1;
            float v2 = acc[mi][ni][2] + b0;
            float v3 = acc[mi][ni][3] + b1;
            if (relu) {
                v0 = fmaxf(v0, 0.0f); v1 = fmaxf(v1, 0.0f);
                v2 = fmaxf(v2, 0.0f); v3 = fmaxf(v3, 0.0f);
            }
            if (c_half) {
                __half* C = (__half*)Cv;
                *(__half2*)&C[(size_t)m * ldc + n]       = __floats2half2_rn(v0, v1);
                *(__half2*)&C[(size_t)(m + 8) * ldc + n] = __floats2half2_rn(v2, v3);
            } else {
                float* C = (float*)Cv;
                *(float2*)&C[(size_t)m * ldc + n]       = make_float2(v0, v1);
                *(float2*)&C[(size_t)(m + 8) * ldc + n] = make_float2(v2, v3);
            }
        }
    }
}

// ---- general GEMM wrapper ---------------------------------------------------
__global__ __launch_bounds__(256, 2)
void gemm_k(const __half* __restrict__ A, int lda, const __half* __restrict__ Bt,
            const float* __restrict__ bias, void* __restrict__ Cv, int ldc,
            int K, int relu, int c_half)
{
    extern __shared__ __half sm[];
    gemm_core(A, lda, Bt, K, bias, Cv, ldc, K, relu, c_half,
              blockIdx.y * BM, blockIdx.x * BN,
              (uint32_t)__cvta_generic_to_shared(sm));
}

// ---- layer-2 pair, z-batched ------------------------------------------------
__global__ __launch_bounds__(256, 2)
void gemm_l2(const __half* __restrict__ hidden, const __half* __restrict__ w2cat,
             const float* __restrict__ b2cat, __half* __restrict__ serelu)
{
    extern __shared__ __half sm[];
    const int z = blockIdx.z;
    gemm_core(hidden + z * 3072, 6144,
              w2cat + (size_t)z * 768 * 3072, 3072,
              b2cat + z * 768,
              serelu + (size_t)z * 4096 * 768, 768,
              3072, 1, 1,
              blockIdx.y * BM, blockIdx.x * BN,
              (uint32_t)__cvta_generic_to_shared(sm));
}

// ---- U/V pair, z-batched (fp16 out); U (z=0) gets ob1 folded in -------------
__global__ __launch_bounds__(256, 2)
void gemm_uv(const __half* __restrict__ serelu, const __half* __restrict__ ow1t,
             const float* __restrict__ ob1, const float* __restrict__ zbias,
             __half* __restrict__ uv)
{
    extern __shared__ __half sm[];
    const int z = blockIdx.z;
    gemm_core(serelu + (size_t)z * 4096 * 768, 768,
              ow1t + z * 768, 1536,           // K-offset into [3072,1536] K-major
              z == 0 ? ob1 : zbias,
              uv + (size_t)z * 4096 * 3072, 3072,
              768, 0, 1,
              blockIdx.y * BM, blockIdx.x * BN,
              (uint32_t)__cvta_generic_to_shared(sm));
}

// ---- gather + add + relu -> fp16 hidden (ob1 already inside U) --------------
//   hidden[r,:] = relu(U[b,i0(r),:] + V[b,i1(r),:])    r in [0,49152)
//   192 threads x 16 halves: 2x uint4 per operand per thread (MLP=4)
__global__ void gather_add_relu(const __half* __restrict__ uv, const int* __restrict__ span,
                                __half* __restrict__ Hout)
{
    const int r  = blockIdx.x;
    const int b  = r / 6144;
    const int c  = threadIdx.x << 4;    // 192 threads x 16 halves
    const int i0 = span[2 * (size_t)r];
    const int i1 = span[2 * (size_t)r + 1];

    const __half* __restrict__ U = uv;
    const __half* __restrict__ V = uv + (size_t)4096 * 3072;
    const __half* up = U + (size_t)(b * 512 + i0) * 3072 + c;
    const __half* vp = V + (size_t)(b * 512 + i1) * 3072 + c;

    uint4 u0 = *(const uint4*)(up);
    uint4 u1 = *(const uint4*)(up + 8);
    uint4 v0 = *(const uint4*)(vp);
    uint4 v1 = *(const uint4*)(vp + 8);

    const __half2 hz = __floats2half2_rn(0.0f, 0.0f);
    uint4 o0, o1;
    const __half2* ua = (const __half2*)&u0;
    const __half2* ub = (const __half2*)&u1;
    const __half2* va = (const __half2*)&v0;
    const __half2* vb = (const __half2*)&v1;
    __half2* oa = (__half2*)&o0;
    __half2* ob = (__half2*)&o1;
#pragma unroll
    for (int j = 0; j < 4; j++) {
        oa[j] = __hmax2(__hadd2(ua[j], va[j]), hz);
        ob[j] = __hmax2(__hadd2(ub[j], vb[j]), hz);
    }
    *(uint4*)&Hout[(size_t)r * 3072 + c]     = o0;
    *(uint4*)&Hout[(size_t)r * 3072 + c + 8] = o1;
}

// ---- fused weight prep: all 6 transposes (+fp16) in ONE launch --------------
__global__ void transpose_all(const float* sw1, const float* ew1, const float* ow1,
                              const float* sw2, const float* ew2, const float* ow2,
                              __half* w1cat, __half* w2cat, __half* ow1t, __half* ow2t)
{
    const float* in; __half* out; int R, C;
    switch (blockIdx.z) {
        case 0: in = sw1; out = w1cat;                          R =  768; C = 3072; break;
        case 1: in = ew1; out = w1cat + (size_t)3072 * 768;     R =  768; C = 3072; break;
        case 2: in = ow1; out = ow1t;                           R = 1536; C = 3072; break;
        case 3: in = sw2; out = w2cat;                          R = 3072; C =  768; break;
        case 4: in = ew2; out = w2cat + (size_t)768 * 3072;     R = 3072; C =  768; break;
        default:in = ow2; out = ow2t;                           R = 3072; C =  768; break;
    }
    const int x0 = blockIdx.x * 32, y0 = blockIdx.y * 32;
    if (x0 >= C || y0 >= R) return;

    __shared__ float t[32][33];
    const int tx = threadIdx.x, ty = threadIdx.y;   // 32 x 8
#pragma unroll
    for (int i = 0; i < 32; i += 8)
        t[ty + i][tx] = in[(size_t)(y0 + ty + i) * C + x0 + tx];
    __syncthreads();
#pragma unroll
    for (int i = 0; i < 32; i += 8)
        out[(size_t)(x0 + ty + i) * R + y0 + tx] = __float2half_rn(t[tx][ty + i]);
}

// ---- bias concats + h convert ----------------------------------------------
__global__ void bias_cat(const float* sb1, const float* eb1, const float* sb2, const float* eb2,
                         float* b1cat, float* b2cat)
{
    int i = blockIdx.x * 256 + threadIdx.x;
    if (i < 3072) { b1cat[i] = sb1[i]; b1cat[3072 + i] = eb1[i]; }
    if (i < 768)  { b2cat[i] = sb2[i]; b2cat[768 + i]  = eb2[i]; }
}

__global__ void f2h_kernel(const float* __restrict__ in, __half* __restrict__ out, int n)
{
    int i = blockIdx.x * 256 + threadIdx.x;
    if (i < n) out[i] = __float2half_rn(in[i]);
}

extern "C" void kernel_launch(void* const* d_in, const int* in_sizes, int n_in,
                              void* d_out, int out_size)
{
    const float* h    = (const float*)d_in[0];
    const int*   span = (const int*)  d_in[1];
    const float* sw1  = (const float*)d_in[2];
    const float* sb1  = (const float*)d_in[3];
    const float* sw2  = (const float*)d_in[4];
    const float* sb2  = (const float*)d_in[5];
    const float* ew1  = (const float*)d_in[6];
    const float* eb1  = (const float*)d_in[7];
    const float* ew2  = (const float*)d_in[8];
    const float* eb2  = (const float*)d_in[9];
    const float* ow1  = (const float*)d_in[10];
    const float* ob1  = (const float*)d_in[11];
    const float* ow2  = (const float*)d_in[12];
    const float* ob2  = (const float*)d_in[13];
    float* out = (float*)d_out;

    __half *hidden, *serelu, *hh, *w1cat, *w2cat, *ow1t, *ow2t, *uv;
    float *b1cat, *b2cat, *zbias;
    cudaGetSymbolAddress((void**)&hidden, g_hidden);
    cudaGetSymbolAddress((void**)&serelu, g_serelu);
    cudaGetSymbolAddress((void**)&hh,     g_hh);
    cudaGetSymbolAddress((void**)&w1cat,  g_w1cat);
    cudaGetSymbolAddress((void**)&w2cat,  g_w2cat);
    cudaGetSymbolAddress((void**)&ow1t,   g_ow1t);
    cudaGetSymbolAddress((void**)&ow2t,   g_ow2t);
    cudaGetSymbolAddress((void**)&uv,     g_uv);
    cudaGetSymbolAddress((void**)&b1cat,  g_b1cat);
    cudaGetSymbolAddress((void**)&b2cat,  g_b2cat);
    cudaGetSymbolAddress((void**)&zbias,  g_zbias);

    cudaFuncSetAttribute(gemm_k,  cudaFuncAttributeMaxDynamicSharedMemorySize, GSMEM_BYTES);
    cudaFuncSetAttribute(gemm_l2, cudaFuncAttributeMaxDynamicSharedMemorySize, GSMEM_BYTES);
    cudaFuncSetAttribute(gemm_uv, cudaFuncAttributeMaxDynamicSharedMemorySize, GSMEM_BYTES);

    // 1: weight transposes   2: bias concats   3: h -> fp16
    transpose_all<<<dim3(96, 96, 6), dim3(32, 8)>>>(sw1, ew1, ow1, sw2, ew2, ow2,
                                                    w1cat, w2cat, ow1t, ow2t);
    bias_cat<<<12, 256>>>(sb1, eb1, sb2, eb2, b1cat, b2cat);
    f2h_kernel<<<(3145728 + 255) / 256, 256>>>(h, hh, 3145728);

    const dim3 blk(256);
    // 4: fused layer-1  hidden_se[4096,6144] = relu(hh @ w1cat + b1cat)
    gemm_k<<<dim3(48, 32), blk, GSMEM_BYTES>>>(hh, 768, w1cat, b1cat, hidden, 6144,
                                               768, 1, 1);
    // 5: batched layer-2  serelu[z] = relu(hidden_se[:, z] @ w2cat[z] + b2cat[z])
    gemm_l2<<<dim3(6, 32, 2), blk, GSMEM_BYTES>>>(hidden, w2cat, b2cat, serelu);
    // 6: U/V projections (fp16); U gets ob1 in epilogue
    gemm_uv<<<dim3(24, 32, 2), blk, GSMEM_BYTES>>>(serelu, ow1t, ob1, zbias, uv);
    // 7: gather + add + relu  hidden[49152,3072] (fp16)
    gather_add_relu<<<49152, 192>>>(uv, span, hidden);
    // 8: final  out[49152,768] = hidden @ ow2t + ob2
    gemm_k<<<dim3(6, 384), blk, GSMEM_BYTES>>>(hidden, 3072, ow2t, ob2, out, 768,
                                               3072, 0, 0);
}